// round 1
// baseline (speedup 1.0000x reference)
#include <cuda_runtime.h>
#include <math.h>

// Problem constants
#define BB 8
#define SS 2048
#define HH 1024
#define MROWS (BB*SS)          // 16384

// ---------------------------------------------------------------------------
// Scratch (allocation-free: __device__ globals)
// ---------------------------------------------------------------------------
__device__ float g_q[(size_t)MROWS * HH];        // raw query  [B*S, H]
__device__ float g_k[(size_t)MROWS * HH];        // raw key    [B*S, H]
__device__ float g_v[(size_t)MROWS * HH];        // value      [B*S, H]
__device__ float g_probs[(size_t)BB * SS * SS];  // softmax(scores)
__device__ float g_cq[BB * HH];                  // ctx @ Wcq^T
__device__ float g_ck[BB * HH];                  // ctx @ Wck^T
__device__ float g_sq[BB];                       // ctx @ g_qc
__device__ float g_sk[BB];                       // ctx @ g_kc
__device__ float g_gq[MROWS];                    // sigmoid gate per (b,s) for Q
__device__ float g_gk[MROWS];                    // sigmoid gate per (b,s) for K

// ---------------------------------------------------------------------------
// Helpers
// ---------------------------------------------------------------------------
__device__ __forceinline__ float warpSum(float v) {
    #pragma unroll
    for (int o = 16; o > 0; o >>= 1) v += __shfl_xor_sync(0xffffffffu, v, o);
    return v;
}
__device__ __forceinline__ float warpMax(float v) {
    #pragma unroll
    for (int o = 16; o > 0; o >>= 1) v = fmaxf(v, __shfl_xor_sync(0xffffffffu, v, o));
    return v;
}

// ---------------------------------------------------------------------------
// K0: per-batch context projections + gate-bias scalars
//   cq[b][o] = sum_h ctx[b][h] * Wcq[o][h]   (ck likewise)
//   sq[b]    = sum_h ctx[b][h] * g_qc[h]     (sk likewise)
// ---------------------------------------------------------------------------
__global__ __launch_bounds__(256) void ctx_kernel(
    const float* __restrict__ ctx, const float* __restrict__ Wcq,
    const float* __restrict__ Wck, const float* __restrict__ gqc,
    const float* __restrict__ gkc)
{
    const int b = blockIdx.x;
    const int t = threadIdx.x;
    __shared__ float cs[HH];
    const float* crow = ctx + (size_t)b * HH;
    for (int i = t; i < HH; i += 256) cs[i] = crow[i];
    __syncthreads();

    for (int o = t; o < HH; o += 256) {
        const float4* wq = (const float4*)(Wcq + (size_t)o * HH);
        const float4* wk = (const float4*)(Wck + (size_t)o * HH);
        float aq = 0.f, ak = 0.f;
        #pragma unroll 4
        for (int h4 = 0; h4 < HH / 4; h4++) {
            float4 w1 = wq[h4], w2 = wk[h4];
            float c0 = cs[h4 * 4 + 0], c1 = cs[h4 * 4 + 1];
            float c2 = cs[h4 * 4 + 2], c3 = cs[h4 * 4 + 3];
            aq += w1.x * c0 + w1.y * c1 + w1.z * c2 + w1.w * c3;
            ak += w2.x * c0 + w2.y * c1 + w2.z * c2 + w2.w * c3;
        }
        g_cq[b * HH + o] = aq;
        g_ck[b * HH + o] = ak;
    }

    float pq = 0.f, pk = 0.f;
    for (int i = t; i < HH; i += 256) { pq += cs[i] * gqc[i]; pk += cs[i] * gkc[i]; }
    __shared__ float rq[8], rk[8];
    pq = warpSum(pq); pk = warpSum(pk);
    if ((t & 31) == 0) { rq[t >> 5] = pq; rk[t >> 5] = pk; }
    __syncthreads();
    if (t == 0) {
        float tq = 0.f, tk = 0.f;
        #pragma unroll
        for (int i = 0; i < 8; i++) { tq += rq[i]; tk += rk[i]; }
        g_sq[b] = tq; g_sk[b] = tk;
    }
}

// ---------------------------------------------------------------------------
// K1: SGEMM (NT): C[M,N] = A[M,K] * W[N,K]^T + bias[N]
//   128x128 block tile, 8x8 per thread, BK=16, 256 threads.
// ---------------------------------------------------------------------------
__global__ __launch_bounds__(256) void sgemm_nt_bias(
    const float* __restrict__ A, const float* __restrict__ W,
    const float* __restrict__ bias, float* __restrict__ C,
    int N, int K)
{
    __shared__ float As[16][128];
    __shared__ float Bs[16][128];
    const int tid = threadIdx.x;
    const int tx = tid & 15;          // 0..15  (N dir)
    const int ty = tid >> 4;          // 0..15  (M dir)
    const int lr = tid >> 2;          // 0..63
    const int lc = (tid & 3) << 2;    // 0,4,8,12

    const float* Ab = A + (size_t)(blockIdx.y * 128) * K;
    const float* Wb = W + (size_t)(blockIdx.x * 128) * K;

    float acc[8][8];
    #pragma unroll
    for (int i = 0; i < 8; i++)
        #pragma unroll
        for (int j = 0; j < 8; j++) acc[i][j] = 0.f;

    for (int kt = 0; kt < K; kt += 16) {
        float4 a0 = *(const float4*)(Ab + (size_t)lr * K + kt + lc);
        float4 a1 = *(const float4*)(Ab + (size_t)(lr + 64) * K + kt + lc);
        float4 b0 = *(const float4*)(Wb + (size_t)lr * K + kt + lc);
        float4 b1 = *(const float4*)(Wb + (size_t)(lr + 64) * K + kt + lc);
        __syncthreads();
        As[lc + 0][lr] = a0.x; As[lc + 1][lr] = a0.y; As[lc + 2][lr] = a0.z; As[lc + 3][lr] = a0.w;
        As[lc + 0][lr + 64] = a1.x; As[lc + 1][lr + 64] = a1.y; As[lc + 2][lr + 64] = a1.z; As[lc + 3][lr + 64] = a1.w;
        Bs[lc + 0][lr] = b0.x; Bs[lc + 1][lr] = b0.y; Bs[lc + 2][lr] = b0.z; Bs[lc + 3][lr] = b0.w;
        Bs[lc + 0][lr + 64] = b1.x; Bs[lc + 1][lr + 64] = b1.y; Bs[lc + 2][lr + 64] = b1.z; Bs[lc + 3][lr + 64] = b1.w;
        __syncthreads();
        #pragma unroll
        for (int k = 0; k < 16; k++) {
            float4 aA = *(const float4*)&As[k][ty * 8];
            float4 aB = *(const float4*)&As[k][ty * 8 + 4];
            float4 bA = *(const float4*)&Bs[k][tx * 8];
            float4 bB = *(const float4*)&Bs[k][tx * 8 + 4];
            float a[8] = {aA.x, aA.y, aA.z, aA.w, aB.x, aB.y, aB.z, aB.w};
            float b[8] = {bA.x, bA.y, bA.z, bA.w, bB.x, bB.y, bB.z, bB.w};
            #pragma unroll
            for (int i = 0; i < 8; i++)
                #pragma unroll
                for (int j = 0; j < 8; j++) acc[i][j] += a[i] * b[j];
        }
    }

    const int row0 = blockIdx.y * 128 + ty * 8;
    const int col0 = blockIdx.x * 128 + tx * 8;
    float4 bi0 = *(const float4*)(bias + col0);
    float4 bi1 = *(const float4*)(bias + col0 + 4);
    #pragma unroll
    for (int i = 0; i < 8; i++) {
        float* cp = C + (size_t)(row0 + i) * N + col0;
        float4 o0 = {acc[i][0] + bi0.x, acc[i][1] + bi0.y, acc[i][2] + bi0.z, acc[i][3] + bi0.w};
        float4 o1 = {acc[i][4] + bi1.x, acc[i][5] + bi1.y, acc[i][6] + bi1.z, acc[i][7] + bi1.w};
        *(float4*)cp = o0;
        *(float4*)(cp + 4) = o1;
    }
}

// ---------------------------------------------------------------------------
// K2: gates: g = sigmoid( row . gvec + s[b] ), one block per (row, q/k)
// ---------------------------------------------------------------------------
__global__ __launch_bounds__(128) void gate_kernel(
    const float* __restrict__ gqh, const float* __restrict__ gkh)
{
    const int r = blockIdx.x;
    const int sel = blockIdx.y;              // 0 -> q, 1 -> k
    const int t = threadIdx.x;
    const float* src = sel ? g_k : g_q;
    const float* gv  = sel ? gkh : gqh;
    const float* sv  = sel ? g_sk : g_sq;
    float* out       = sel ? g_gk : g_gq;

    const float4* row = (const float4*)(src + (size_t)r * HH);
    const float4* gg  = (const float4*)gv;
    float p = 0.f;
    #pragma unroll
    for (int i = t; i < HH / 4; i += 128) {
        float4 a = row[i], b = gg[i];
        p += a.x * b.x + a.y * b.y + a.z * b.z + a.w * b.w;
    }
    p = warpSum(p);
    __shared__ float red[4];
    if ((t & 31) == 0) red[t >> 5] = p;
    __syncthreads();
    if (t == 0) {
        float tot = red[0] + red[1] + red[2] + red[3];
        int b = r >> 11;                     // r / S
        out[r] = 1.f / (1.f + expf(-(tot + sv[b])));
    }
}

// ---------------------------------------------------------------------------
// K3: scores GEMM per batch with on-the-fly gating:
//   qhat = (1-g)*q + g*cq[b],  khat likewise
//   scores[b][q][k] = (qhat . khat) / 32
// ---------------------------------------------------------------------------
__global__ __launch_bounds__(256) void scores_gemm(float* __restrict__ scores_out)
{
    __shared__ float As[16][128];
    __shared__ float Bs[16][128];
    const int z = blockIdx.z;
    const int tid = threadIdx.x;
    const int tx = tid & 15, ty = tid >> 4;
    const int lr = tid >> 2, lc = (tid & 3) << 2;

    const float* Qb = g_q + (size_t)z * SS * HH + (size_t)(blockIdx.y * 128) * HH;
    const float* Kb = g_k + (size_t)z * SS * HH + (size_t)(blockIdx.x * 128) * HH;
    const float* cq = g_cq + z * HH;
    const float* ck = g_ck + z * HH;
    const float* gq = g_gq + z * SS;
    const float* gk = g_gk + z * SS;

    const int ar0 = blockIdx.y * 128 + lr, ar1 = ar0 + 64;
    const int br0 = blockIdx.x * 128 + lr, br1 = br0 + 64;
    const float ga0 = gq[ar0], ga1 = gq[ar1];
    const float gb0 = gk[br0], gb1 = gk[br1];

    float acc[8][8];
    #pragma unroll
    for (int i = 0; i < 8; i++)
        #pragma unroll
        for (int j = 0; j < 8; j++) acc[i][j] = 0.f;

    for (int kt = 0; kt < HH; kt += 16) {
        float4 q0 = *(const float4*)(Qb + (size_t)lr * HH + kt + lc);
        float4 q1 = *(const float4*)(Qb + (size_t)(lr + 64) * HH + kt + lc);
        float4 k0 = *(const float4*)(Kb + (size_t)lr * HH + kt + lc);
        float4 k1 = *(const float4*)(Kb + (size_t)(lr + 64) * HH + kt + lc);
        float4 c4 = *(const float4*)(cq + kt + lc);
        float4 d4 = *(const float4*)(ck + kt + lc);
        // qhat = q + g*(c - q)
        float4 a0 = {q0.x + ga0 * (c4.x - q0.x), q0.y + ga0 * (c4.y - q0.y),
                     q0.z + ga0 * (c4.z - q0.z), q0.w + ga0 * (c4.w - q0.w)};
        float4 a1 = {q1.x + ga1 * (c4.x - q1.x), q1.y + ga1 * (c4.y - q1.y),
                     q1.z + ga1 * (c4.z - q1.z), q1.w + ga1 * (c4.w - q1.w)};
        float4 b0 = {k0.x + gb0 * (d4.x - k0.x), k0.y + gb0 * (d4.y - k0.y),
                     k0.z + gb0 * (d4.z - k0.z), k0.w + gb0 * (d4.w - k0.w)};
        float4 b1 = {k1.x + gb1 * (d4.x - k1.x), k1.y + gb1 * (d4.y - k1.y),
                     k1.z + gb1 * (d4.z - k1.z), k1.w + gb1 * (d4.w - k1.w)};
        __syncthreads();
        As[lc + 0][lr] = a0.x; As[lc + 1][lr] = a0.y; As[lc + 2][lr] = a0.z; As[lc + 3][lr] = a0.w;
        As[lc + 0][lr + 64] = a1.x; As[lc + 1][lr + 64] = a1.y; As[lc + 2][lr + 64] = a1.z; As[lc + 3][lr + 64] = a1.w;
        Bs[lc + 0][lr] = b0.x; Bs[lc + 1][lr] = b0.y; Bs[lc + 2][lr] = b0.z; Bs[lc + 3][lr] = b0.w;
        Bs[lc + 0][lr + 64] = b1.x; Bs[lc + 1][lr + 64] = b1.y; Bs[lc + 2][lr + 64] = b1.z; Bs[lc + 3][lr + 64] = b1.w;
        __syncthreads();
        #pragma unroll
        for (int k = 0; k < 16; k++) {
            float4 aA = *(const float4*)&As[k][ty * 8];
            float4 aB = *(const float4*)&As[k][ty * 8 + 4];
            float4 bA = *(const float4*)&Bs[k][tx * 8];
            float4 bB = *(const float4*)&Bs[k][tx * 8 + 4];
            float a[8] = {aA.x, aA.y, aA.z, aA.w, aB.x, aB.y, aB.z, aB.w};
            float b[8] = {bA.x, bA.y, bA.z, bA.w, bB.x, bB.y, bB.z, bB.w};
            #pragma unroll
            for (int i = 0; i < 8; i++)
                #pragma unroll
                for (int j = 0; j < 8; j++) acc[i][j] += a[i] * b[j];
        }
    }

    const float scale = 0.03125f;   // 1/sqrt(1024)
    float* Cb = scores_out + (size_t)z * SS * SS;
    const int row0 = blockIdx.y * 128 + ty * 8;
    const int col0 = blockIdx.x * 128 + tx * 8;
    #pragma unroll
    for (int i = 0; i < 8; i++) {
        float* cp = Cb + (size_t)(row0 + i) * SS + col0;
        float4 o0 = {acc[i][0] * scale, acc[i][1] * scale, acc[i][2] * scale, acc[i][3] * scale};
        float4 o1 = {acc[i][4] * scale, acc[i][5] * scale, acc[i][6] * scale, acc[i][7] * scale};
        *(float4*)cp = o0;
        *(float4*)(cp + 4) = o1;
    }
}

// ---------------------------------------------------------------------------
// K4: softmax over each scores row -> g_probs. One block per row.
// ---------------------------------------------------------------------------
__global__ __launch_bounds__(256) void softmax_rows(const float* __restrict__ scores)
{
    const int row = blockIdx.x;                       // 0 .. B*S-1
    const int t = threadIdx.x;
    const float4* src = (const float4*)(scores + (size_t)row * SS);
    float4* dst = (float4*)(g_probs + (size_t)row * SS);

    float4 v0 = src[t], v1 = src[t + 256];
    float m = fmaxf(fmaxf(fmaxf(v0.x, v0.y), fmaxf(v0.z, v0.w)),
                    fmaxf(fmaxf(v1.x, v1.y), fmaxf(v1.z, v1.w)));
    m = warpMax(m);
    __shared__ float rm[8], rs[8];
    if ((t & 31) == 0) rm[t >> 5] = m;
    __syncthreads();
    float mm = rm[0];
    #pragma unroll
    for (int i = 1; i < 8; i++) mm = fmaxf(mm, rm[i]);

    float4 e0 = {expf(v0.x - mm), expf(v0.y - mm), expf(v0.z - mm), expf(v0.w - mm)};
    float4 e1 = {expf(v1.x - mm), expf(v1.y - mm), expf(v1.z - mm), expf(v1.w - mm)};
    float s = e0.x + e0.y + e0.z + e0.w + e1.x + e1.y + e1.z + e1.w;
    s = warpSum(s);
    if ((t & 31) == 0) rs[t >> 5] = s;
    __syncthreads();
    float tot = rs[0];
    #pragma unroll
    for (int i = 1; i < 8; i++) tot += rs[i];
    const float inv = 1.f / tot;

    float4 p0 = {e0.x * inv, e0.y * inv, e0.z * inv, e0.w * inv};
    float4 p1 = {e1.x * inv, e1.y * inv, e1.z * inv, e1.w * inv};
    dst[t] = p0;
    dst[t + 256] = p1;
}

// ---------------------------------------------------------------------------
// K5: out = P @ V per batch (NN GEMM). A = probs [S,S], B = V [S,H].
// ---------------------------------------------------------------------------
__global__ __launch_bounds__(256) void out_gemm(float* __restrict__ out)
{
    __shared__ float As[16][128];
    __shared__ float Bs[16][128];
    const int z = blockIdx.z;
    const int tid = threadIdx.x;
    const int tx = tid & 15, ty = tid >> 4;
    const int lr = tid >> 2, lc = (tid & 3) << 2;
    const int br = tid >> 4;                 // 0..15 (B-tile row = k)
    const int bc = (tid & 15) << 2;          // 0..60

    const float* Ab = g_probs + (size_t)z * SS * SS + (size_t)(blockIdx.y * 128) * SS;
    const float* Vb = g_v + (size_t)z * SS * HH;
    const int colBase = blockIdx.x * 128;

    float acc[8][8];
    #pragma unroll
    for (int i = 0; i < 8; i++)
        #pragma unroll
        for (int j = 0; j < 8; j++) acc[i][j] = 0.f;

    for (int kt = 0; kt < SS; kt += 16) {
        float4 a0 = *(const float4*)(Ab + (size_t)lr * SS + kt + lc);
        float4 a1 = *(const float4*)(Ab + (size_t)(lr + 64) * SS + kt + lc);
        float4 v0 = *(const float4*)(Vb + (size_t)(kt + br) * HH + colBase + bc);
        float4 v1 = *(const float4*)(Vb + (size_t)(kt + br) * HH + colBase + bc + 64);
        __syncthreads();
        As[lc + 0][lr] = a0.x; As[lc + 1][lr] = a0.y; As[lc + 2][lr] = a0.z; As[lc + 3][lr] = a0.w;
        As[lc + 0][lr + 64] = a1.x; As[lc + 1][lr + 64] = a1.y; As[lc + 2][lr + 64] = a1.z; As[lc + 3][lr + 64] = a1.w;
        *(float4*)&Bs[br][bc] = v0;
        *(float4*)&Bs[br][bc + 64] = v1;
        __syncthreads();
        #pragma unroll
        for (int k = 0; k < 16; k++) {
            float4 aA = *(const float4*)&As[k][ty * 8];
            float4 aB = *(const float4*)&As[k][ty * 8 + 4];
            float4 bA = *(const float4*)&Bs[k][tx * 8];
            float4 bB = *(const float4*)&Bs[k][tx * 8 + 4];
            float a[8] = {aA.x, aA.y, aA.z, aA.w, aB.x, aB.y, aB.z, aB.w};
            float b[8] = {bA.x, bA.y, bA.z, bA.w, bB.x, bB.y, bB.z, bB.w};
            #pragma unroll
            for (int i = 0; i < 8; i++)
                #pragma unroll
                for (int j = 0; j < 8; j++) acc[i][j] += a[i] * b[j];
        }
    }

    float* Ob = out + (size_t)z * SS * HH;
    const int row0 = blockIdx.y * 128 + ty * 8;
    const int col0 = colBase + tx * 8;
    #pragma unroll
    for (int i = 0; i < 8; i++) {
        float* cp = Ob + (size_t)(row0 + i) * HH + col0;
        float4 o0 = {acc[i][0], acc[i][1], acc[i][2], acc[i][3]};
        float4 o1 = {acc[i][4], acc[i][5], acc[i][6], acc[i][7]};
        *(float4*)cp = o0;
        *(float4*)(cp + 4) = o1;
    }
}

// ---------------------------------------------------------------------------
// Launch
// ---------------------------------------------------------------------------
extern "C" void kernel_launch(void* const* d_in, const int* in_sizes, int n_in,
                              void* d_out, int out_size)
{
    const float* hidden = (const float*)d_in[0];
    const float* ctx    = (const float*)d_in[1];
    const float* Wq     = (const float*)d_in[2];
    const float* bq     = (const float*)d_in[3];
    const float* Wk     = (const float*)d_in[4];
    const float* bk     = (const float*)d_in[5];
    const float* Wv     = (const float*)d_in[6];
    const float* bv     = (const float*)d_in[7];
    const float* Wcq    = (const float*)d_in[8];
    const float* Wck    = (const float*)d_in[9];
    const float* gqh    = (const float*)d_in[10];
    const float* gkh    = (const float*)d_in[11];
    const float* gqc    = (const float*)d_in[12];
    const float* gkc    = (const float*)d_in[13];

    float* out        = (float*)d_out;                          // [B,S,H]
    float* scores_out = out + (size_t)BB * SS * HH;             // [B,S,S]

    // Resolve scratch symbols (host-side queries; graph-capture safe)
    float *pq, *pk, *pv;
    cudaGetSymbolAddress((void**)&pq, g_q);
    cudaGetSymbolAddress((void**)&pk, g_k);
    cudaGetSymbolAddress((void**)&pv, g_v);

    // K0: context projections + scalars
    ctx_kernel<<<BB, 256>>>(ctx, Wcq, Wck, gqc, gkc);

    // K1: Q/K/V projections
    dim3 gQKV(HH / 128, MROWS / 128);
    sgemm_nt_bias<<<gQKV, 256>>>(hidden, Wq, bq, pq, HH, HH);
    sgemm_nt_bias<<<gQKV, 256>>>(hidden, Wk, bk, pk, HH, HH);
    sgemm_nt_bias<<<gQKV, 256>>>(hidden, Wv, bv, pv, HH, HH);

    // K2: gates
    gate_kernel<<<dim3(MROWS, 2), 128>>>(gqh, gkh);

    // K3: scores (gating applied on-the-fly in tile loads)
    scores_gemm<<<dim3(SS / 128, SS / 128, BB), 256>>>(scores_out);

    // K4: softmax rows
    softmax_rows<<<BB * SS, 256>>>(scores_out);

    // K5: out = P @ V
    out_gemm<<<dim3(HH / 128, SS / 128, BB), 256>>>(out);
}

// round 4
// speedup vs baseline: 2.1288x; 2.1288x over previous
#include <cuda_runtime.h>
#include <cuda_bf16.h>
#include <math.h>
#include <stdint.h>

// Problem constants
#define BB 8
#define SS 2048
#define HH 1024
#define MROWS (BB*SS)          // 16384

// ---------------------------------------------------------------------------
// Scratch (allocation-free: __device__ globals)
// ---------------------------------------------------------------------------
__device__ float g_q[(size_t)MROWS * HH];        // query -> qhat (in place)
__device__ float g_k[(size_t)MROWS * HH];        // key   -> khat (in place)
__device__ float g_v[(size_t)MROWS * HH];        // value
__device__ float g_vt[(size_t)BB * HH * SS];     // V^T per batch [H, S]
__device__ float g_probs[(size_t)BB * SS * SS];  // softmax(scores)
__device__ float g_cq[BB * HH];                  // ctx @ Wcq^T
__device__ float g_ck[BB * HH];                  // ctx @ Wck^T
__device__ float g_sq[BB];                       // ctx @ g_qc
__device__ float g_sk[BB];                       // ctx @ g_kc

// ---------------------------------------------------------------------------
// Helpers
// ---------------------------------------------------------------------------
__device__ __forceinline__ float warpSum(float v) {
    #pragma unroll
    for (int o = 16; o > 0; o >>= 1) v += __shfl_xor_sync(0xffffffffu, v, o);
    return v;
}
__device__ __forceinline__ float warpMax(float v) {
    #pragma unroll
    for (int o = 16; o > 0; o >>= 1) v = fmaxf(v, __shfl_xor_sync(0xffffffffu, v, o));
    return v;
}

__device__ __forceinline__ uint32_t pack_bf2(float a, float b) {
    __nv_bfloat162 t = __floats2bfloat162_rn(a, b);   // .x = a (low half)
    return *(uint32_t*)&t;
}

// Split a float4 into bf16-hi (packed 2x u32) and bf16-lo
__device__ __forceinline__ void split4(float4 v, uint32_t* hi, uint32_t* lo) {
    float hx = __bfloat162float(__float2bfloat16_rn(v.x));
    float hy = __bfloat162float(__float2bfloat16_rn(v.y));
    float hz = __bfloat162float(__float2bfloat16_rn(v.z));
    float hw = __bfloat162float(__float2bfloat16_rn(v.w));
    hi[0] = pack_bf2(hx, hy);         hi[1] = pack_bf2(hz, hw);
    lo[0] = pack_bf2(v.x - hx, v.y - hy);
    lo[1] = pack_bf2(v.z - hz, v.w - hw);
}

// bf16 tensor-core mma: D(f32) += A(bf16 m16k16) * B(bf16 n8k16)^T
__device__ __forceinline__ void mma_bf16(float* d, const uint32_t* a, const uint32_t* b) {
    asm volatile(
        "mma.sync.aligned.m16n8k16.row.col.f32.bf16.bf16.f32 "
        "{%0,%1,%2,%3}, {%4,%5,%6,%7}, {%8,%9}, {%0,%1,%2,%3};"
        : "+f"(d[0]), "+f"(d[1]), "+f"(d[2]), "+f"(d[3])
        : "r"(a[0]), "r"(a[1]), "r"(a[2]), "r"(a[3]), "r"(b[0]), "r"(b[1]));
}

// ---------------------------------------------------------------------------
// GEMM: C[M,N] = alpha * (A[M,K] @ B[N,K]^T) + bias[N]; batched via blockIdx.z.
// bf16 split (hi+lo, 3 products), mma.sync m16n8k16, fp32 accumulate.
// 128x128 tile, BK=32, 256 threads (8 warps, warp tile 64x32).
// ---------------------------------------------------------------------------
#define SROW 40   // smem row stride in bf16 elems (80B: conflict-free frag loads)

__global__ __launch_bounds__(256, 2) void gemm_bf16s(
    const float* __restrict__ A, const float* __restrict__ B,
    const float* __restrict__ bias, float* __restrict__ C,
    float alpha, int N, int K,
    long long bA, long long bB, long long bC)
{
    __shared__ __nv_bfloat16 sAh[128 * SROW];
    __shared__ __nv_bfloat16 sAl[128 * SROW];
    __shared__ __nv_bfloat16 sBh[128 * SROW];
    __shared__ __nv_bfloat16 sBl[128 * SROW];

    const int tid = threadIdx.x;
    const int lane = tid & 31, wid = tid >> 5;
    const int z = blockIdx.z;
    const int n0 = blockIdx.x * 128, m0 = blockIdx.y * 128;
    A += (size_t)bA * z;  B += (size_t)bB * z;  C += (size_t)bC * z;

    // Loader coords: 32 rows per j-step, 8 float4 columns
    const int lr = tid >> 3;            // 0..31
    const int lc = (tid & 7) * 4;       // 0,4,...,28
    const float* aptr = A + (size_t)(m0 + lr) * K + lc;
    const float* bptr = B + (size_t)(n0 + lr) * K + lc;

    // Warp tile: 64(M) x 32(N)
    const int wm = (wid >> 2) * 64;     // 0 or 64
    const int wn = (wid & 3) * 32;      // 0,32,64,96
    const int fr = lane >> 2;           // 0..7
    const int fk = (lane & 3) * 2;      // 0,2,4,6

    float acc[4][4][4];
    #pragma unroll
    for (int mi = 0; mi < 4; mi++)
        #pragma unroll
        for (int ni = 0; ni < 4; ni++)
            #pragma unroll
            for (int r = 0; r < 4; r++) acc[mi][ni][r] = 0.f;

    const int T = K >> 5;
    float4 av[4], bv[4];
    #pragma unroll
    for (int j = 0; j < 4; j++) {
        av[j] = *(const float4*)(aptr + (size_t)(32 * j) * K);
        bv[j] = *(const float4*)(bptr + (size_t)(32 * j) * K);
    }

    for (int t = 0; t < T; t++) {
        // Store current tile (f32 -> bf16 hi/lo) into smem
        #pragma unroll
        for (int j = 0; j < 4; j++) {
            const int off = (lr + 32 * j) * SROW + lc;
            uint32_t h[2], l[2];
            split4(av[j], h, l);
            *(uint2*)(sAh + off) = make_uint2(h[0], h[1]);
            *(uint2*)(sAl + off) = make_uint2(l[0], l[1]);
            split4(bv[j], h, l);
            *(uint2*)(sBh + off) = make_uint2(h[0], h[1]);
            *(uint2*)(sBl + off) = make_uint2(l[0], l[1]);
        }
        __syncthreads();

        // Prefetch next tile into registers
        if (t + 1 < T) {
            const int kt = (t + 1) << 5;
            #pragma unroll
            for (int j = 0; j < 4; j++) {
                av[j] = *(const float4*)(aptr + (size_t)(32 * j) * K + kt);
                bv[j] = *(const float4*)(bptr + (size_t)(32 * j) * K + kt);
            }
        }

        // Compute: 2 k16 steps
        #pragma unroll
        for (int ks = 0; ks < 2; ks++) {
            const int kb = ks * 16;
            uint32_t bh[4][2], bl[4][2];
            #pragma unroll
            for (int ni = 0; ni < 4; ni++) {
                const int nr = (wn + ni * 8 + fr) * SROW + kb + fk;
                bh[ni][0] = *(const uint32_t*)(sBh + nr);
                bh[ni][1] = *(const uint32_t*)(sBh + nr + 8);
                bl[ni][0] = *(const uint32_t*)(sBl + nr);
                bl[ni][1] = *(const uint32_t*)(sBl + nr + 8);
            }
            #pragma unroll
            for (int mi = 0; mi < 4; mi++) {
                const int mr0 = (wm + mi * 16 + fr) * SROW + kb + fk;
                const int mr8 = mr0 + 8 * SROW;
                uint32_t ah[4], al[4];
                ah[0] = *(const uint32_t*)(sAh + mr0);
                ah[1] = *(const uint32_t*)(sAh + mr8);
                ah[2] = *(const uint32_t*)(sAh + mr0 + 8);
                ah[3] = *(const uint32_t*)(sAh + mr8 + 8);
                al[0] = *(const uint32_t*)(sAl + mr0);
                al[1] = *(const uint32_t*)(sAl + mr8);
                al[2] = *(const uint32_t*)(sAl + mr0 + 8);
                al[3] = *(const uint32_t*)(sAl + mr8 + 8);
                #pragma unroll
                for (int ni = 0; ni < 4; ni++) {
                    mma_bf16(acc[mi][ni], ah, bh[ni]);
                    mma_bf16(acc[mi][ni], ah, bl[ni]);
                    mma_bf16(acc[mi][ni], al, bh[ni]);
                }
            }
        }
        __syncthreads();
    }

    // Epilogue
    #pragma unroll
    for (int mi = 0; mi < 4; mi++) {
        const int r = m0 + wm + mi * 16 + fr;
        #pragma unroll
        for (int ni = 0; ni < 4; ni++) {
            const int c = n0 + wn + ni * 8 + (lane & 3) * 2;
            float b0 = 0.f, b1 = 0.f;
            if (bias) { b0 = bias[c]; b1 = bias[c + 1]; }
            float2 o0 = {acc[mi][ni][0] * alpha + b0, acc[mi][ni][1] * alpha + b1};
            float2 o1 = {acc[mi][ni][2] * alpha + b0, acc[mi][ni][3] * alpha + b1};
            *(float2*)(C + (size_t)r * N + c) = o0;
            *(float2*)(C + (size_t)(r + 8) * N + c) = o1;
        }
    }
}

// ---------------------------------------------------------------------------
// K0: per-batch context projections + gate-bias scalars
// ---------------------------------------------------------------------------
__global__ __launch_bounds__(256) void ctx_kernel(
    const float* __restrict__ ctx, const float* __restrict__ Wcq,
    const float* __restrict__ Wck, const float* __restrict__ gqc,
    const float* __restrict__ gkc)
{
    const int b = blockIdx.x;
    const int t = threadIdx.x;
    __shared__ float cs[HH];
    const float* crow = ctx + (size_t)b * HH;
    for (int i = t; i < HH; i += 256) cs[i] = crow[i];
    __syncthreads();

    for (int o = t; o < HH; o += 256) {
        const float4* wq = (const float4*)(Wcq + (size_t)o * HH);
        const float4* wk = (const float4*)(Wck + (size_t)o * HH);
        float aq = 0.f, ak = 0.f;
        #pragma unroll 4
        for (int h4 = 0; h4 < HH / 4; h4++) {
            float4 w1 = wq[h4], w2 = wk[h4];
            float e0 = cs[h4 * 4 + 0], e1 = cs[h4 * 4 + 1];
            float e2 = cs[h4 * 4 + 2], e3 = cs[h4 * 4 + 3];
            aq += w1.x * e0 + w1.y * e1 + w1.z * e2 + w1.w * e3;
            ak += w2.x * e0 + w2.y * e1 + w2.z * e2 + w2.w * e3;
        }
        g_cq[b * HH + o] = aq;
        g_ck[b * HH + o] = ak;
    }

    float pq = 0.f, pk = 0.f;
    for (int i = t; i < HH; i += 256) { pq += cs[i] * gqc[i]; pk += cs[i] * gkc[i]; }
    __shared__ float rq[8], rk[8];
    pq = warpSum(pq); pk = warpSum(pk);
    if ((t & 31) == 0) { rq[t >> 5] = pq; rk[t >> 5] = pk; }
    __syncthreads();
    if (t == 0) {
        float tq = 0.f, tk = 0.f;
        #pragma unroll
        for (int i = 0; i < 8; i++) { tq += rq[i]; tk += rk[i]; }
        g_sq[b] = tq; g_sk[b] = tk;
    }
}

// ---------------------------------------------------------------------------
// Fused gate + hat (in place): g = sigmoid(row.gvec + s[b]);
//     row = row + g*(ctx_proj - row)
// ---------------------------------------------------------------------------
__global__ __launch_bounds__(256) void gate_hat_kernel(
    const float* __restrict__ gqh, const float* __restrict__ gkh)
{
    const int r = blockIdx.x;
    const int sel = blockIdx.y;
    const int t = threadIdx.x;
    float* src       = sel ? g_k : g_q;
    const float* gv  = sel ? gkh : gqh;
    const float* sv  = sel ? g_sk : g_sq;
    const int b = r >> 11;
    const float* cp  = (sel ? g_ck : g_cq) + b * HH;

    float4* rowp = (float4*)(src + (size_t)r * HH);
    float4 v = rowp[t];
    float4 gw = ((const float4*)gv)[t];
    float p = v.x * gw.x + v.y * gw.y + v.z * gw.z + v.w * gw.w;
    p = warpSum(p);
    __shared__ float red[8];
    __shared__ float gsh;
    if ((t & 31) == 0) red[t >> 5] = p;
    __syncthreads();
    if (t == 0) {
        float tot = 0.f;
        #pragma unroll
        for (int i = 0; i < 8; i++) tot += red[i];
        gsh = 1.f / (1.f + expf(-(tot + sv[b])));
    }
    __syncthreads();
    const float g = gsh;
    float4 c = ((const float4*)cp)[t];
    v.x += g * (c.x - v.x); v.y += g * (c.y - v.y);
    v.z += g * (c.z - v.z); v.w += g * (c.w - v.w);
    rowp[t] = v;
}

// ---------------------------------------------------------------------------
// V transpose per batch: g_vt[z][h][s] = g_v[z][s][h]
// ---------------------------------------------------------------------------
__global__ __launch_bounds__(256) void transpose_v()
{
    __shared__ float tile[32][33];
    const int z = blockIdx.z;
    const int s0 = blockIdx.x * 32, h0 = blockIdx.y * 32;
    const float* src = g_v + (size_t)z * SS * HH;
    float* dst = g_vt + (size_t)z * HH * SS;
    const int tx = threadIdx.x, ty = threadIdx.y;
    #pragma unroll
    for (int i = ty; i < 32; i += 8)
        tile[i][tx] = src[(size_t)(s0 + i) * HH + h0 + tx];
    __syncthreads();
    #pragma unroll
    for (int i = ty; i < 32; i += 8)
        dst[(size_t)(h0 + i) * SS + s0 + tx] = tile[tx][i];
}

// ---------------------------------------------------------------------------
// Softmax over each scores row -> g_probs. One block per row.
// ---------------------------------------------------------------------------
__global__ __launch_bounds__(256) void softmax_rows(const float* __restrict__ scores)
{
    const int row = blockIdx.x;
    const int t = threadIdx.x;
    const float4* src = (const float4*)(scores + (size_t)row * SS);
    float4* dst = (float4*)(g_probs + (size_t)row * SS);

    float4 v0 = src[t], v1 = src[t + 256];
    float m = fmaxf(fmaxf(fmaxf(v0.x, v0.y), fmaxf(v0.z, v0.w)),
                    fmaxf(fmaxf(v1.x, v1.y), fmaxf(v1.z, v1.w)));
    m = warpMax(m);
    __shared__ float rm[8], rs[8];
    if ((t & 31) == 0) rm[t >> 5] = m;
    __syncthreads();
    float mm = rm[0];
    #pragma unroll
    for (int i = 1; i < 8; i++) mm = fmaxf(mm, rm[i]);

    float4 e0 = {expf(v0.x - mm), expf(v0.y - mm), expf(v0.z - mm), expf(v0.w - mm)};
    float4 e1 = {expf(v1.x - mm), expf(v1.y - mm), expf(v1.z - mm), expf(v1.w - mm)};
    float s = e0.x + e0.y + e0.z + e0.w + e1.x + e1.y + e1.z + e1.w;
    s = warpSum(s);
    if ((t & 31) == 0) rs[t >> 5] = s;
    __syncthreads();
    float tot = rs[0];
    #pragma unroll
    for (int i = 1; i < 8; i++) tot += rs[i];
    const float inv = 1.f / tot;

    float4 p0 = {e0.x * inv, e0.y * inv, e0.z * inv, e0.w * inv};
    float4 p1 = {e1.x * inv, e1.y * inv, e1.z * inv, e1.w * inv};
    dst[t] = p0;
    dst[t + 256] = p1;
}

// ---------------------------------------------------------------------------
// Launch
// ---------------------------------------------------------------------------
extern "C" void kernel_launch(void* const* d_in, const int* in_sizes, int n_in,
                              void* d_out, int out_size)
{
    const float* hidden = (const float*)d_in[0];
    const float* ctx    = (const float*)d_in[1];
    const float* Wq     = (const float*)d_in[2];
    const float* bq     = (const float*)d_in[3];
    const float* Wk     = (const float*)d_in[4];
    const float* bk     = (const float*)d_in[5];
    const float* Wv     = (const float*)d_in[6];
    const float* bv     = (const float*)d_in[7];
    const float* Wcq    = (const float*)d_in[8];
    const float* Wck    = (const float*)d_in[9];
    const float* gqh    = (const float*)d_in[10];
    const float* gkh    = (const float*)d_in[11];
    const float* gqc    = (const float*)d_in[12];
    const float* gkc    = (const float*)d_in[13];

    float* out        = (float*)d_out;                 // [B,S,H]
    float* scores_out = out + (size_t)BB * SS * HH;    // [B,S,S]

    float *pq, *pk, *pv, *pvt, *pp;
    cudaGetSymbolAddress((void**)&pq,  g_q);
    cudaGetSymbolAddress((void**)&pk,  g_k);
    cudaGetSymbolAddress((void**)&pv,  g_v);
    cudaGetSymbolAddress((void**)&pvt, g_vt);
    cudaGetSymbolAddress((void**)&pp,  g_probs);

    // K0: context projections + scalars
    ctx_kernel<<<BB, 256>>>(ctx, Wcq, Wck, gqc, gkc);

    // QKV projections: C = hidden @ W^T + bias   [16384,1024]
    dim3 gQKV(HH / 128, MROWS / 128, 1);
    gemm_bf16s<<<gQKV, 256>>>(hidden, Wq, bq, pq, 1.f, HH, HH, 0, 0, 0);
    gemm_bf16s<<<gQKV, 256>>>(hidden, Wk, bk, pk, 1.f, HH, HH, 0, 0, 0);
    gemm_bf16s<<<gQKV, 256>>>(hidden, Wv, bv, pv, 1.f, HH, HH, 0, 0, 0);

    // Gate + hat (in place on g_q / g_k)
    gate_hat_kernel<<<dim3(MROWS, 2), 256>>>(gqh, gkh);

    // V transpose for PV GEMM
    transpose_v<<<dim3(SS / 32, HH / 32, BB), dim3(32, 8)>>>();

    // scores = qhat @ khat^T * 1/32   per batch
    gemm_bf16s<<<dim3(SS / 128, SS / 128, BB), 256>>>(
        pq, pk, nullptr, scores_out, 0.03125f, SS, HH,
        (long long)SS * HH, (long long)SS * HH, (long long)SS * SS);

    // softmax
    softmax_rows<<<BB * SS, 256>>>(scores_out);

    // out = probs @ V = probs @ (V^T)^T   per batch
    gemm_bf16s<<<dim3(HH / 128, SS / 128, BB), 256>>>(
        pp, pvt, nullptr, out, 1.f, HH, SS,
        (long long)SS * SS, (long long)HH * SS, (long long)SS * HH);
}

// round 5
// speedup vs baseline: 2.1779x; 1.0231x over previous
#include <cuda_runtime.h>
#include <cuda_bf16.h>
#include <math.h>
#include <stdint.h>

// Problem constants
#define BB 8
#define SS 2048
#define HH 1024
#define MROWS (BB*SS)          // 16384

// ---------------------------------------------------------------------------
// Scratch (allocation-free: __device__ globals)
// ---------------------------------------------------------------------------
__device__ float g_q[(size_t)MROWS * HH];        // raw query (fp32, from proj)
__device__ float g_k[(size_t)MROWS * HH];        // raw key
__device__ float g_v[(size_t)MROWS * HH];        // value
__device__ __nv_bfloat16 g_qh[(size_t)MROWS * HH];  // qhat hi
__device__ __nv_bfloat16 g_ql[(size_t)MROWS * HH];  // qhat lo
__device__ __nv_bfloat16 g_kh[(size_t)MROWS * HH];  // khat hi
__device__ __nv_bfloat16 g_kl[(size_t)MROWS * HH];  // khat lo
__device__ __nv_bfloat16 g_vth[(size_t)BB * HH * SS]; // V^T hi [H,S]
__device__ __nv_bfloat16 g_vtl[(size_t)BB * HH * SS]; // V^T lo
__device__ __nv_bfloat16 g_ph[(size_t)BB * SS * SS];  // probs hi
__device__ __nv_bfloat16 g_pl[(size_t)BB * SS * SS];  // probs lo
__device__ float g_cq[BB * HH];
__device__ float g_ck[BB * HH];
__device__ float g_sq[BB];
__device__ float g_sk[BB];

// ---------------------------------------------------------------------------
// Helpers
// ---------------------------------------------------------------------------
__device__ __forceinline__ float warpSum(float v) {
    #pragma unroll
    for (int o = 16; o > 0; o >>= 1) v += __shfl_xor_sync(0xffffffffu, v, o);
    return v;
}
__device__ __forceinline__ float warpMax(float v) {
    #pragma unroll
    for (int o = 16; o > 0; o >>= 1) v = fmaxf(v, __shfl_xor_sync(0xffffffffu, v, o));
    return v;
}

__device__ __forceinline__ uint32_t pack_bf2(float a, float b) {
    __nv_bfloat162 t = __floats2bfloat162_rn(a, b);   // .x = a (low half)
    return *(uint32_t*)&t;
}

// Split a float4 into bf16-hi (packed 2x u32) and bf16-lo
__device__ __forceinline__ void split4(float4 v, uint32_t* hi, uint32_t* lo) {
    float hx = __bfloat162float(__float2bfloat16_rn(v.x));
    float hy = __bfloat162float(__float2bfloat16_rn(v.y));
    float hz = __bfloat162float(__float2bfloat16_rn(v.z));
    float hw = __bfloat162float(__float2bfloat16_rn(v.w));
    hi[0] = pack_bf2(hx, hy);         hi[1] = pack_bf2(hz, hw);
    lo[0] = pack_bf2(v.x - hx, v.y - hy);
    lo[1] = pack_bf2(v.z - hz, v.w - hw);
}

// bf16 tensor-core mma: D(f32) += A(bf16 m16k16) * B(bf16 n8k16)^T
__device__ __forceinline__ void mma_bf16(float* d, const uint32_t* a, const uint32_t* b) {
    asm volatile(
        "mma.sync.aligned.m16n8k16.row.col.f32.bf16.bf16.f32 "
        "{%0,%1,%2,%3}, {%4,%5,%6,%7}, {%8,%9}, {%0,%1,%2,%3};"
        : "+f"(d[0]), "+f"(d[1]), "+f"(d[2]), "+f"(d[3])
        : "r"(a[0]), "r"(a[1]), "r"(a[2]), "r"(a[3]), "r"(b[0]), "r"(b[1]));
}

__device__ __forceinline__ void ldsm4(uint32_t* r, uint32_t addr) {
    asm volatile("ldmatrix.sync.aligned.m8n8.x4.shared.b16 {%0,%1,%2,%3}, [%4];"
        : "=r"(r[0]), "=r"(r[1]), "=r"(r[2]), "=r"(r[3]) : "r"(addr));
}

// ---------------------------------------------------------------------------
// Shared tile-compute body: 128x128 tile, BK=32, 8 warps (warp 64x32).
// smem operands in SROW-stride bf16 layout; fragments via ldmatrix.x4.
// ---------------------------------------------------------------------------
#define SROW 40            // smem row stride in bf16 elems (80B, conflict-free)
#define MI_STRIDE 1280     // 16 rows * SROW * 2B

__device__ __forceinline__ void mma_tile(
    uint32_t sAh_b, uint32_t sAl_b, uint32_t sBh_b, uint32_t sBl_b,
    uint32_t aoff, uint32_t boff, float acc[4][4][4])
{
    #pragma unroll
    for (int ks = 0; ks < 2; ks++) {
        uint32_t bh[4][2], bl[4][2], t[4];
        #pragma unroll
        for (int np = 0; np < 2; np++) {
            const uint32_t o = boff + np * MI_STRIDE + ks * 32;
            ldsm4(t, sBh_b + o);
            bh[2*np][0] = t[0]; bh[2*np][1] = t[1];
            bh[2*np+1][0] = t[2]; bh[2*np+1][1] = t[3];
            ldsm4(t, sBl_b + o);
            bl[2*np][0] = t[0]; bl[2*np][1] = t[1];
            bl[2*np+1][0] = t[2]; bl[2*np+1][1] = t[3];
        }
        #pragma unroll
        for (int mi = 0; mi < 4; mi++) {
            const uint32_t o = aoff + mi * MI_STRIDE + ks * 32;
            uint32_t ah[4], al[4];
            ldsm4(ah, sAh_b + o);
            ldsm4(al, sAl_b + o);
            #pragma unroll
            for (int ni = 0; ni < 4; ni++) {
                mma_bf16(acc[mi][ni], ah, bh[ni]);
                mma_bf16(acc[mi][ni], ah, bl[ni]);
                mma_bf16(acc[mi][ni], al, bh[ni]);
            }
        }
    }
}

// ldmatrix per-lane offsets (bytes) within warp tile
__device__ __forceinline__ uint32_t ldsm_aoff(int wm, int lane) {
    const int r = (lane & 7) + ((lane >> 3) & 1) * 8;   // row in 16-row group
    const int c = (lane >> 4) * 8;                      // k offset 0/8
    return (uint32_t)(((wm + r) * SROW + c) * 2);
}
__device__ __forceinline__ uint32_t ldsm_boff(int wn, int lane) {
    const int r = (lane & 7) + (lane >> 4) * 8;         // n row in 16-row group
    const int c = ((lane >> 3) & 1) * 8;                // k offset 0/8
    return (uint32_t)(((wn + r) * SROW + c) * 2);
}

// ---------------------------------------------------------------------------
// GEMM A (fp32 inputs, split in loader): C = alpha*(A@B^T)+bias. QKV projections.
// ---------------------------------------------------------------------------
__global__ __launch_bounds__(256, 2) void gemm_f32in(
    const float* __restrict__ A, const float* __restrict__ B,
    const float* __restrict__ bias, float* __restrict__ C,
    float alpha, int N, int K)
{
    __shared__ __nv_bfloat16 sAh[128 * SROW];
    __shared__ __nv_bfloat16 sAl[128 * SROW];
    __shared__ __nv_bfloat16 sBh[128 * SROW];
    __shared__ __nv_bfloat16 sBl[128 * SROW];

    const int tid = threadIdx.x;
    const int lane = tid & 31, wid = tid >> 5;
    const int n0 = blockIdx.x * 128, m0 = blockIdx.y * 128;

    const int lr = tid >> 3;            // 0..31
    const int lc = (tid & 7) * 4;       // 0,4,...,28
    const float* aptr = A + (size_t)(m0 + lr) * K + lc;
    const float* bptr = B + (size_t)(n0 + lr) * K + lc;

    const int wm = (wid >> 2) * 64;
    const int wn = (wid & 3) * 32;
    const uint32_t sAh_b = (uint32_t)__cvta_generic_to_shared(sAh);
    const uint32_t sAl_b = (uint32_t)__cvta_generic_to_shared(sAl);
    const uint32_t sBh_b = (uint32_t)__cvta_generic_to_shared(sBh);
    const uint32_t sBl_b = (uint32_t)__cvta_generic_to_shared(sBl);
    const uint32_t aoff = ldsm_aoff(wm, lane);
    const uint32_t boff = ldsm_boff(wn, lane);

    float acc[4][4][4];
    #pragma unroll
    for (int mi = 0; mi < 4; mi++)
        #pragma unroll
        for (int ni = 0; ni < 4; ni++)
            #pragma unroll
            for (int r = 0; r < 4; r++) acc[mi][ni][r] = 0.f;

    const int T = K >> 5;
    float4 av[4], bv[4];
    #pragma unroll
    for (int j = 0; j < 4; j++) {
        av[j] = *(const float4*)(aptr + (size_t)(32 * j) * K);
        bv[j] = *(const float4*)(bptr + (size_t)(32 * j) * K);
    }

    for (int t = 0; t < T; t++) {
        #pragma unroll
        for (int j = 0; j < 4; j++) {
            const int off = (lr + 32 * j) * SROW + lc;
            uint32_t h[2], l[2];
            split4(av[j], h, l);
            *(uint2*)(sAh + off) = make_uint2(h[0], h[1]);
            *(uint2*)(sAl + off) = make_uint2(l[0], l[1]);
            split4(bv[j], h, l);
            *(uint2*)(sBh + off) = make_uint2(h[0], h[1]);
            *(uint2*)(sBl + off) = make_uint2(l[0], l[1]);
        }
        __syncthreads();

        if (t + 1 < T) {
            const int kt = (t + 1) << 5;
            #pragma unroll
            for (int j = 0; j < 4; j++) {
                av[j] = *(const float4*)(aptr + (size_t)(32 * j) * K + kt);
                bv[j] = *(const float4*)(bptr + (size_t)(32 * j) * K + kt);
            }
        }

        mma_tile(sAh_b, sAl_b, sBh_b, sBl_b, aoff, boff, acc);
        __syncthreads();
    }

    const int fr = lane >> 2;
    #pragma unroll
    for (int mi = 0; mi < 4; mi++) {
        const int r = m0 + wm + mi * 16 + fr;
        #pragma unroll
        for (int ni = 0; ni < 4; ni++) {
            const int c = n0 + wn + ni * 8 + (lane & 3) * 2;
            const float b0 = bias[c], b1 = bias[c + 1];
            float2 o0 = {acc[mi][ni][0] * alpha + b0, acc[mi][ni][1] * alpha + b1};
            float2 o1 = {acc[mi][ni][2] * alpha + b0, acc[mi][ni][3] * alpha + b1};
            *(float2*)(C + (size_t)r * N + c) = o0;
            *(float2*)(C + (size_t)(r + 8) * N + c) = o1;
        }
    }
}

// ---------------------------------------------------------------------------
// GEMM B (pre-split bf16 hi/lo inputs): C = alpha*(A@B^T); batched via blockIdx.z.
// Loader is a pure uint4 copy — no convert math.
// ---------------------------------------------------------------------------
__global__ __launch_bounds__(256, 2) void gemm_pre(
    const __nv_bfloat16* __restrict__ Ah, const __nv_bfloat16* __restrict__ Al,
    const __nv_bfloat16* __restrict__ Bh, const __nv_bfloat16* __restrict__ Bl,
    float* __restrict__ C, float alpha, int N, int K,
    long long bA, long long bB, long long bC)
{
    __shared__ __nv_bfloat16 sAh[128 * SROW];
    __shared__ __nv_bfloat16 sAl[128 * SROW];
    __shared__ __nv_bfloat16 sBh[128 * SROW];
    __shared__ __nv_bfloat16 sBl[128 * SROW];

    const int tid = threadIdx.x;
    const int lane = tid & 31, wid = tid >> 5;
    const int z = blockIdx.z;
    const int n0 = blockIdx.x * 128, m0 = blockIdx.y * 128;
    Ah += (size_t)bA * z;  Al += (size_t)bA * z;
    Bh += (size_t)bB * z;  Bl += (size_t)bB * z;
    C  += (size_t)bC * z;

    const int lr = tid >> 2;            // 0..63
    const int lc = (tid & 3) * 8;       // 0,8,16,24 (bf16 elems)
    const __nv_bfloat16* pah = Ah + (size_t)(m0 + lr) * K + lc;
    const __nv_bfloat16* pal = Al + (size_t)(m0 + lr) * K + lc;
    const __nv_bfloat16* pbh = Bh + (size_t)(n0 + lr) * K + lc;
    const __nv_bfloat16* pbl = Bl + (size_t)(n0 + lr) * K + lc;

    const int wm = (wid >> 2) * 64;
    const int wn = (wid & 3) * 32;
    const uint32_t sAh_b = (uint32_t)__cvta_generic_to_shared(sAh);
    const uint32_t sAl_b = (uint32_t)__cvta_generic_to_shared(sAl);
    const uint32_t sBh_b = (uint32_t)__cvta_generic_to_shared(sBh);
    const uint32_t sBl_b = (uint32_t)__cvta_generic_to_shared(sBl);
    const uint32_t aoff = ldsm_aoff(wm, lane);
    const uint32_t boff = ldsm_boff(wn, lane);

    float acc[4][4][4];
    #pragma unroll
    for (int mi = 0; mi < 4; mi++)
        #pragma unroll
        for (int ni = 0; ni < 4; ni++)
            #pragma unroll
            for (int r = 0; r < 4; r++) acc[mi][ni][r] = 0.f;

    const int T = K >> 5;
    uint4 vah[2], val[2], vbh[2], vbl[2];
    #pragma unroll
    for (int j = 0; j < 2; j++) {
        vah[j] = *(const uint4*)(pah + (size_t)(64 * j) * K);
        val[j] = *(const uint4*)(pal + (size_t)(64 * j) * K);
        vbh[j] = *(const uint4*)(pbh + (size_t)(64 * j) * K);
        vbl[j] = *(const uint4*)(pbl + (size_t)(64 * j) * K);
    }

    for (int t = 0; t < T; t++) {
        #pragma unroll
        for (int j = 0; j < 2; j++) {
            const int off = (lr + 64 * j) * SROW + lc;
            *(uint4*)(sAh + off) = vah[j];
            *(uint4*)(sAl + off) = val[j];
            *(uint4*)(sBh + off) = vbh[j];
            *(uint4*)(sBl + off) = vbl[j];
        }
        __syncthreads();

        if (t + 1 < T) {
            const int kt = (t + 1) << 5;
            #pragma unroll
            for (int j = 0; j < 2; j++) {
                vah[j] = *(const uint4*)(pah + (size_t)(64 * j) * K + kt);
                val[j] = *(const uint4*)(pal + (size_t)(64 * j) * K + kt);
                vbh[j] = *(const uint4*)(pbh + (size_t)(64 * j) * K + kt);
                vbl[j] = *(const uint4*)(pbl + (size_t)(64 * j) * K + kt);
            }
        }

        mma_tile(sAh_b, sAl_b, sBh_b, sBl_b, aoff, boff, acc);
        __syncthreads();
    }

    const int fr = lane >> 2;
    #pragma unroll
    for (int mi = 0; mi < 4; mi++) {
        const int r = m0 + wm + mi * 16 + fr;
        #pragma unroll
        for (int ni = 0; ni < 4; ni++) {
            const int c = n0 + wn + ni * 8 + (lane & 3) * 2;
            float2 o0 = {acc[mi][ni][0] * alpha, acc[mi][ni][1] * alpha};
            float2 o1 = {acc[mi][ni][2] * alpha, acc[mi][ni][3] * alpha};
            *(float2*)(C + (size_t)r * N + c) = o0;
            *(float2*)(C + (size_t)(r + 8) * N + c) = o1;
        }
    }
}

// ---------------------------------------------------------------------------
// K0: per-batch context projections + gate-bias scalars
// ---------------------------------------------------------------------------
__global__ __launch_bounds__(256) void ctx_kernel(
    const float* __restrict__ ctx, const float* __restrict__ Wcq,
    const float* __restrict__ Wck, const float* __restrict__ gqc,
    const float* __restrict__ gkc)
{
    const int b = blockIdx.x;
    const int t = threadIdx.x;
    __shared__ float cs[HH];
    const float* crow = ctx + (size_t)b * HH;
    for (int i = t; i < HH; i += 256) cs[i] = crow[i];
    __syncthreads();

    for (int o = t; o < HH; o += 256) {
        const float4* wq = (const float4*)(Wcq + (size_t)o * HH);
        const float4* wk = (const float4*)(Wck + (size_t)o * HH);
        float aq = 0.f, ak = 0.f;
        #pragma unroll 4
        for (int h4 = 0; h4 < HH / 4; h4++) {
            float4 w1 = wq[h4], w2 = wk[h4];
            float e0 = cs[h4 * 4 + 0], e1 = cs[h4 * 4 + 1];
            float e2 = cs[h4 * 4 + 2], e3 = cs[h4 * 4 + 3];
            aq += w1.x * e0 + w1.y * e1 + w1.z * e2 + w1.w * e3;
            ak += w2.x * e0 + w2.y * e1 + w2.z * e2 + w2.w * e3;
        }
        g_cq[b * HH + o] = aq;
        g_ck[b * HH + o] = ak;
    }

    float pq = 0.f, pk = 0.f;
    for (int i = t; i < HH; i += 256) { pq += cs[i] * gqc[i]; pk += cs[i] * gkc[i]; }
    __shared__ float rq[8], rk[8];
    pq = warpSum(pq); pk = warpSum(pk);
    if ((t & 31) == 0) { rq[t >> 5] = pq; rk[t >> 5] = pk; }
    __syncthreads();
    if (t == 0) {
        float tq = 0.f, tk = 0.f;
        #pragma unroll
        for (int i = 0; i < 8; i++) { tq += rq[i]; tk += rk[i]; }
        g_sq[b] = tq; g_sk[b] = tk;
    }
}

// ---------------------------------------------------------------------------
// Fused gate + hat: g = sigmoid(row.gvec + s[b]);
//   hat = row + g*(ctx_proj - row), written directly as bf16 hi/lo.
// ---------------------------------------------------------------------------
__global__ __launch_bounds__(256) void gate_hat_kernel(
    const float* __restrict__ gqh_w, const float* __restrict__ gkh_w)
{
    const int r = blockIdx.x;
    const int sel = blockIdx.y;
    const int t = threadIdx.x;
    const float* src = sel ? g_k : g_q;
    const float* gv  = sel ? gkh_w : gqh_w;
    const float* sv  = sel ? g_sk : g_sq;
    const int b = r >> 11;
    const float* cp  = (sel ? g_ck : g_cq) + b * HH;
    __nv_bfloat16* dsth = sel ? g_kh : g_qh;
    __nv_bfloat16* dstl = sel ? g_kl : g_ql;

    const float4* rowp = (const float4*)(src + (size_t)r * HH);
    float4 v = rowp[t];
    float4 gw = ((const float4*)gv)[t];
    float p = v.x * gw.x + v.y * gw.y + v.z * gw.z + v.w * gw.w;
    p = warpSum(p);
    __shared__ float red[8];
    __shared__ float gsh;
    if ((t & 31) == 0) red[t >> 5] = p;
    __syncthreads();
    if (t == 0) {
        float tot = 0.f;
        #pragma unroll
        for (int i = 0; i < 8; i++) tot += red[i];
        gsh = 1.f / (1.f + expf(-(tot + sv[b])));
    }
    __syncthreads();
    const float g = gsh;
    float4 c = ((const float4*)cp)[t];
    v.x += g * (c.x - v.x); v.y += g * (c.y - v.y);
    v.z += g * (c.z - v.z); v.w += g * (c.w - v.w);

    uint32_t h[2], l[2];
    split4(v, h, l);
    *(uint2*)(dsth + (size_t)r * HH + 4 * t) = make_uint2(h[0], h[1]);
    *(uint2*)(dstl + (size_t)r * HH + 4 * t) = make_uint2(l[0], l[1]);
}

// ---------------------------------------------------------------------------
// V transpose per batch into bf16 hi/lo: g_vt*[z][h][s] = split(g_v[z][s][h])
// ---------------------------------------------------------------------------
__global__ __launch_bounds__(256) void transpose_v()
{
    __shared__ float tile[32][33];
    const int z = blockIdx.z;
    const int s0 = blockIdx.x * 32, h0 = blockIdx.y * 32;
    const float* src = g_v + (size_t)z * SS * HH;
    __nv_bfloat16* dh = g_vth + (size_t)z * HH * SS;
    __nv_bfloat16* dl = g_vtl + (size_t)z * HH * SS;
    const int tx = threadIdx.x, ty = threadIdx.y;
    #pragma unroll
    for (int i = ty; i < 32; i += 8)
        tile[i][tx] = src[(size_t)(s0 + i) * HH + h0 + tx];
    __syncthreads();
    #pragma unroll
    for (int i = ty; i < 32; i += 8) {
        const float v = tile[tx][i];
        const __nv_bfloat16 hb = __float2bfloat16_rn(v);
        dh[(size_t)(h0 + i) * SS + s0 + tx] = hb;
        dl[(size_t)(h0 + i) * SS + s0 + tx] = __float2bfloat16_rn(v - __bfloat162float(hb));
    }
}

// ---------------------------------------------------------------------------
// Softmax over each scores row -> probs bf16 hi/lo. One block per row.
// ---------------------------------------------------------------------------
__global__ __launch_bounds__(256) void softmax_rows(const float* __restrict__ scores)
{
    const int row = blockIdx.x;
    const int t = threadIdx.x;
    const float4* src = (const float4*)(scores + (size_t)row * SS);
    __nv_bfloat16* dh = g_ph + (size_t)row * SS;
    __nv_bfloat16* dl = g_pl + (size_t)row * SS;

    float4 v0 = src[t], v1 = src[t + 256];
    float m = fmaxf(fmaxf(fmaxf(v0.x, v0.y), fmaxf(v0.z, v0.w)),
                    fmaxf(fmaxf(v1.x, v1.y), fmaxf(v1.z, v1.w)));
    m = warpMax(m);
    __shared__ float rm[8], rs[8];
    if ((t & 31) == 0) rm[t >> 5] = m;
    __syncthreads();
    float mm = rm[0];
    #pragma unroll
    for (int i = 1; i < 8; i++) mm = fmaxf(mm, rm[i]);

    float4 e0 = {expf(v0.x - mm), expf(v0.y - mm), expf(v0.z - mm), expf(v0.w - mm)};
    float4 e1 = {expf(v1.x - mm), expf(v1.y - mm), expf(v1.z - mm), expf(v1.w - mm)};
    float s = e0.x + e0.y + e0.z + e0.w + e1.x + e1.y + e1.z + e1.w;
    s = warpSum(s);
    if ((t & 31) == 0) rs[t >> 5] = s;
    __syncthreads();
    float tot = rs[0];
    #pragma unroll
    for (int i = 1; i < 8; i++) tot += rs[i];
    const float inv = 1.f / tot;

    float4 p0 = {e0.x * inv, e0.y * inv, e0.z * inv, e0.w * inv};
    float4 p1 = {e1.x * inv, e1.y * inv, e1.z * inv, e1.w * inv};
    uint32_t h[2], l[2];
    split4(p0, h, l);
    *(uint2*)(dh + 4 * t) = make_uint2(h[0], h[1]);
    *(uint2*)(dl + 4 * t) = make_uint2(l[0], l[1]);
    split4(p1, h, l);
    *(uint2*)(dh + 1024 + 4 * t) = make_uint2(h[0], h[1]);
    *(uint2*)(dl + 1024 + 4 * t) = make_uint2(l[0], l[1]);
}

// ---------------------------------------------------------------------------
// Launch
// ---------------------------------------------------------------------------
extern "C" void kernel_launch(void* const* d_in, const int* in_sizes, int n_in,
                              void* d_out, int out_size)
{
    const float* hidden = (const float*)d_in[0];
    const float* ctx    = (const float*)d_in[1];
    const float* Wq     = (const float*)d_in[2];
    const float* bq     = (const float*)d_in[3];
    const float* Wk     = (const float*)d_in[4];
    const float* bk     = (const float*)d_in[5];
    const float* Wv     = (const float*)d_in[6];
    const float* bv     = (const float*)d_in[7];
    const float* Wcq    = (const float*)d_in[8];
    const float* Wck    = (const float*)d_in[9];
    const float* gqh_w  = (const float*)d_in[10];
    const float* gkh_w  = (const float*)d_in[11];
    const float* gqc    = (const float*)d_in[12];
    const float* gkc    = (const float*)d_in[13];

    float* out        = (float*)d_out;                 // [B,S,H]
    float* scores_out = out + (size_t)BB * SS * HH;    // [B,S,S]

    float *pq, *pk, *pv;
    __nv_bfloat16 *pqh, *pql, *pkh, *pkl, *pvth, *pvtl, *pph, *ppl;
    cudaGetSymbolAddress((void**)&pq,  g_q);
    cudaGetSymbolAddress((void**)&pk,  g_k);
    cudaGetSymbolAddress((void**)&pv,  g_v);
    cudaGetSymbolAddress((void**)&pqh, g_qh);
    cudaGetSymbolAddress((void**)&pql, g_ql);
    cudaGetSymbolAddress((void**)&pkh, g_kh);
    cudaGetSymbolAddress((void**)&pkl, g_kl);
    cudaGetSymbolAddress((void**)&pvth, g_vth);
    cudaGetSymbolAddress((void**)&pvtl, g_vtl);
    cudaGetSymbolAddress((void**)&pph, g_ph);
    cudaGetSymbolAddress((void**)&ppl, g_pl);

    // K0: context projections + scalars
    ctx_kernel<<<BB, 256>>>(ctx, Wcq, Wck, gqc, gkc);

    // QKV projections: fp32 in, fp32 out
    dim3 gQKV(HH / 128, MROWS / 128, 1);
    gemm_f32in<<<gQKV, 256>>>(hidden, Wq, bq, pq, 1.f, HH, HH);
    gemm_f32in<<<gQKV, 256>>>(hidden, Wk, bk, pk, 1.f, HH, HH);
    gemm_f32in<<<gQKV, 256>>>(hidden, Wv, bv, pv, 1.f, HH, HH);

    // Gate + hat -> bf16 hi/lo
    gate_hat_kernel<<<dim3(MROWS, 2), 256>>>(gqh_w, gkh_w);

    // V transpose -> bf16 hi/lo
    transpose_v<<<dim3(SS / 32, HH / 32, BB), dim3(32, 8)>>>();

    // scores = qhat @ khat^T * 1/32 per batch (pre-split operands)
    gemm_pre<<<dim3(SS / 128, SS / 128, BB), 256>>>(
        pqh, pql, pkh, pkl, scores_out, 0.03125f, SS, HH,
        (long long)SS * HH, (long long)SS * HH, (long long)SS * SS);

    // softmax -> probs bf16 hi/lo
    softmax_rows<<<BB * SS, 256>>>(scores_out);

    // out = probs @ V = probs @ (V^T)^T per batch (pre-split operands)
    gemm_pre<<<dim3(HH / 128, SS / 128, BB), 256>>>(
        pph, ppl, pvth, pvtl, out, 1.f, HH, SS,
        (long long)SS * SS, (long long)HH * SS, (long long)SS * HH);
}

// round 6
// speedup vs baseline: 2.4109x; 1.1070x over previous
#include <cuda_runtime.h>
#include <cuda_bf16.h>
#include <math.h>
#include <stdint.h>

// Problem constants
#define BB 8
#define SS 2048
#define HH 1024
#define MROWS (BB*SS)          // 16384

// ---------------------------------------------------------------------------
// Scratch (allocation-free: __device__ globals)
// ---------------------------------------------------------------------------
__device__ float g_q[(size_t)MROWS * HH];        // raw query (fp32, from proj)
__device__ float g_k[(size_t)MROWS * HH];        // raw key
__device__ float g_v[(size_t)MROWS * HH];        // value
__device__ __nv_bfloat16 g_hh[(size_t)MROWS * HH];  // hidden hi
__device__ __nv_bfloat16 g_hl[(size_t)MROWS * HH];  // hidden lo
__device__ __nv_bfloat16 g_wqh[HH * HH], g_wql[HH * HH];
__device__ __nv_bfloat16 g_wkh[HH * HH], g_wkl[HH * HH];
__device__ __nv_bfloat16 g_wvh[HH * HH], g_wvl[HH * HH];
__device__ __nv_bfloat16 g_qh[(size_t)MROWS * HH];  // qhat hi
__device__ __nv_bfloat16 g_ql[(size_t)MROWS * HH];  // qhat lo
__device__ __nv_bfloat16 g_kh[(size_t)MROWS * HH];  // khat hi
__device__ __nv_bfloat16 g_kl[(size_t)MROWS * HH];  // khat lo
__device__ __nv_bfloat16 g_vth[(size_t)BB * HH * SS]; // V^T hi [H,S]
__device__ __nv_bfloat16 g_vtl[(size_t)BB * HH * SS]; // V^T lo
__device__ __nv_bfloat16 g_ph[(size_t)BB * SS * SS];  // probs hi
__device__ __nv_bfloat16 g_pl[(size_t)BB * SS * SS];  // probs lo
__device__ float g_cq[BB * HH];
__device__ float g_ck[BB * HH];
__device__ float g_sq[BB];
__device__ float g_sk[BB];

// ---------------------------------------------------------------------------
// Helpers
// ---------------------------------------------------------------------------
__device__ __forceinline__ float warpSum(float v) {
    #pragma unroll
    for (int o = 16; o > 0; o >>= 1) v += __shfl_xor_sync(0xffffffffu, v, o);
    return v;
}
__device__ __forceinline__ float warpMax(float v) {
    #pragma unroll
    for (int o = 16; o > 0; o >>= 1) v = fmaxf(v, __shfl_xor_sync(0xffffffffu, v, o));
    return v;
}

__device__ __forceinline__ uint32_t pack_bf2(float a, float b) {
    __nv_bfloat162 t = __floats2bfloat162_rn(a, b);   // .x = a (low half)
    return *(uint32_t*)&t;
}

// Split a float4 into bf16-hi (packed 2x u32) and bf16-lo
__device__ __forceinline__ void split4(float4 v, uint32_t* hi, uint32_t* lo) {
    float hx = __bfloat162float(__float2bfloat16_rn(v.x));
    float hy = __bfloat162float(__float2bfloat16_rn(v.y));
    float hz = __bfloat162float(__float2bfloat16_rn(v.z));
    float hw = __bfloat162float(__float2bfloat16_rn(v.w));
    hi[0] = pack_bf2(hx, hy);         hi[1] = pack_bf2(hz, hw);
    lo[0] = pack_bf2(v.x - hx, v.y - hy);
    lo[1] = pack_bf2(v.z - hz, v.w - hw);
}

// bf16 tensor-core mma: D(f32) += A(bf16 m16k16) * B(bf16 n8k16)^T
__device__ __forceinline__ void mma_bf16(float* d, const uint32_t* a, const uint32_t* b) {
    asm volatile(
        "mma.sync.aligned.m16n8k16.row.col.f32.bf16.bf16.f32 "
        "{%0,%1,%2,%3}, {%4,%5,%6,%7}, {%8,%9}, {%0,%1,%2,%3};"
        : "+f"(d[0]), "+f"(d[1]), "+f"(d[2]), "+f"(d[3])
        : "r"(a[0]), "r"(a[1]), "r"(a[2]), "r"(a[3]), "r"(b[0]), "r"(b[1]));
}

__device__ __forceinline__ void ldsm4(uint32_t* r, uint32_t addr) {
    asm volatile("ldmatrix.sync.aligned.m8n8.x4.shared.b16 {%0,%1,%2,%3}, [%4];"
        : "=r"(r[0]), "=r"(r[1]), "=r"(r[2]), "=r"(r[3]) : "r"(addr));
}

__device__ __forceinline__ void cpasync16(uint32_t saddr, const void* g) {
    asm volatile("cp.async.cg.shared.global [%0], [%1], 16;" :: "r"(saddr), "l"(g));
}
#define CP_COMMIT() asm volatile("cp.async.commit_group;" ::: "memory")
#define CP_WAIT0()  asm volatile("cp.async.wait_group 0;" ::: "memory")
#define CP_WAIT1()  asm volatile("cp.async.wait_group 1;" ::: "memory")

// ---------------------------------------------------------------------------
// Shared tile-compute body: 128x128 tile, BK=32, 8 warps (warp 64x32).
// ---------------------------------------------------------------------------
#define SROW 40            // smem row stride in bf16 elems (80B, conflict-free)
#define MI_STRIDE 1280     // 16 rows * SROW * 2B
#define ARR_BYTES 10240    // 128 * SROW * 2
#define STAGE_BYTES 40960  // 4 arrays

__device__ __forceinline__ void mma_tile(
    uint32_t sAh_b, uint32_t sAl_b, uint32_t sBh_b, uint32_t sBl_b,
    uint32_t aoff, uint32_t boff, float acc[4][4][4])
{
    #pragma unroll
    for (int ks = 0; ks < 2; ks++) {
        uint32_t bh[4][2], bl[4][2], t[4];
        #pragma unroll
        for (int np = 0; np < 2; np++) {
            const uint32_t o = boff + np * MI_STRIDE + ks * 32;
            ldsm4(t, sBh_b + o);
            bh[2*np][0] = t[0]; bh[2*np][1] = t[1];
            bh[2*np+1][0] = t[2]; bh[2*np+1][1] = t[3];
            ldsm4(t, sBl_b + o);
            bl[2*np][0] = t[0]; bl[2*np][1] = t[1];
            bl[2*np+1][0] = t[2]; bl[2*np+1][1] = t[3];
        }
        #pragma unroll
        for (int mi = 0; mi < 4; mi++) {
            const uint32_t o = aoff + mi * MI_STRIDE + ks * 32;
            uint32_t ah[4], al[4];
            ldsm4(ah, sAh_b + o);
            ldsm4(al, sAl_b + o);
            #pragma unroll
            for (int ni = 0; ni < 4; ni++) {
                mma_bf16(acc[mi][ni], ah, bh[ni]);
                mma_bf16(acc[mi][ni], ah, bl[ni]);
                mma_bf16(acc[mi][ni], al, bh[ni]);
            }
        }
    }
}

// ldmatrix per-lane offsets (bytes) within warp tile
__device__ __forceinline__ uint32_t ldsm_aoff(int wm, int lane) {
    const int r = (lane & 7) + ((lane >> 3) & 1) * 8;
    const int c = (lane >> 4) * 8;
    return (uint32_t)(((wm + r) * SROW + c) * 2);
}
__device__ __forceinline__ uint32_t ldsm_boff(int wn, int lane) {
    const int r = (lane & 7) + (lane >> 4) * 8;
    const int c = ((lane >> 3) & 1) * 8;
    return (uint32_t)(((wn + r) * SROW + c) * 2);
}

// ---------------------------------------------------------------------------
// Unified GEMM (pre-split bf16 hi/lo inputs, cp.async double-buffered):
//   C = alpha*(A@B^T) + bias; batched via blockIdx.z.
// ---------------------------------------------------------------------------
__global__ __launch_bounds__(256, 2) void gemm_pre(
    const __nv_bfloat16* __restrict__ Ah, const __nv_bfloat16* __restrict__ Al,
    const __nv_bfloat16* __restrict__ Bh, const __nv_bfloat16* __restrict__ Bl,
    const float* __restrict__ bias, float* __restrict__ C,
    float alpha, int N, int K,
    long long bA, long long bB, long long bC)
{
    extern __shared__ __nv_bfloat16 dsm[];
    const uint32_t base = (uint32_t)__cvta_generic_to_shared(dsm);

    const int tid = threadIdx.x;
    const int lane = tid & 31, wid = tid >> 5;
    const int z = blockIdx.z;
    const int n0 = blockIdx.x * 128, m0 = blockIdx.y * 128;
    Ah += (size_t)bA * z;  Al += (size_t)bA * z;
    Bh += (size_t)bB * z;  Bl += (size_t)bB * z;
    C  += (size_t)bC * z;

    const int lr = tid >> 2;            // 0..63
    const int lc = (tid & 3) * 8;       // 0,8,16,24 (bf16 elems; 16B)
    const __nv_bfloat16* pah = Ah + (size_t)(m0 + lr) * K + lc;
    const __nv_bfloat16* pal = Al + (size_t)(m0 + lr) * K + lc;
    const __nv_bfloat16* pbh = Bh + (size_t)(n0 + lr) * K + lc;
    const __nv_bfloat16* pbl = Bl + (size_t)(n0 + lr) * K + lc;
    const uint32_t soff0 = (uint32_t)((lr * SROW + lc) * 2);
    const uint32_t soff1 = (uint32_t)(((lr + 64) * SROW + lc) * 2);

    const int wm = (wid >> 2) * 64;
    const int wn = (wid & 3) * 32;
    const uint32_t aoff = ldsm_aoff(wm, lane);
    const uint32_t boff = ldsm_boff(wn, lane);

    float acc[4][4][4];
    #pragma unroll
    for (int mi = 0; mi < 4; mi++)
        #pragma unroll
        for (int ni = 0; ni < 4; ni++)
            #pragma unroll
            for (int r = 0; r < 4; r++) acc[mi][ni][r] = 0.f;

    const int T = K >> 5;

    // Issue async loads for tile t into stage s
    auto issue = [&](int t, int s) {
        const int kt = t << 5;
        const uint32_t sb = base + (uint32_t)s * STAGE_BYTES;
        cpasync16(sb + 0*ARR_BYTES + soff0, pah + kt);
        cpasync16(sb + 0*ARR_BYTES + soff1, pah + (size_t)64 * K + kt);
        cpasync16(sb + 1*ARR_BYTES + soff0, pal + kt);
        cpasync16(sb + 1*ARR_BYTES + soff1, pal + (size_t)64 * K + kt);
        cpasync16(sb + 2*ARR_BYTES + soff0, pbh + kt);
        cpasync16(sb + 2*ARR_BYTES + soff1, pbh + (size_t)64 * K + kt);
        cpasync16(sb + 3*ARR_BYTES + soff0, pbl + kt);
        cpasync16(sb + 3*ARR_BYTES + soff1, pbl + (size_t)64 * K + kt);
    };

    issue(0, 0);
    CP_COMMIT();

    for (int t = 0; t < T; t++) {
        if (t + 1 < T) {
            issue(t + 1, (t + 1) & 1);
            CP_COMMIT();
            CP_WAIT1();          // tile t's group complete; t+1 may be in flight
        } else {
            CP_WAIT0();
        }
        __syncthreads();

        const uint32_t sb = base + (uint32_t)(t & 1) * STAGE_BYTES;
        mma_tile(sb + 0*ARR_BYTES, sb + 1*ARR_BYTES,
                 sb + 2*ARR_BYTES, sb + 3*ARR_BYTES, aoff, boff, acc);
        __syncthreads();         // stage (t&1) free for tile t+2's loads
    }

    const int fr = lane >> 2;
    #pragma unroll
    for (int mi = 0; mi < 4; mi++) {
        const int r = m0 + wm + mi * 16 + fr;
        #pragma unroll
        for (int ni = 0; ni < 4; ni++) {
            const int c = n0 + wn + ni * 8 + (lane & 3) * 2;
            float b0 = 0.f, b1 = 0.f;
            if (bias) { b0 = bias[c]; b1 = bias[c + 1]; }
            float2 o0 = {acc[mi][ni][0] * alpha + b0, acc[mi][ni][1] * alpha + b1};
            float2 o1 = {acc[mi][ni][2] * alpha + b0, acc[mi][ni][3] * alpha + b1};
            *(float2*)(C + (size_t)r * N + c) = o0;
            *(float2*)(C + (size_t)(r + 8) * N + c) = o1;
        }
    }
}

// ---------------------------------------------------------------------------
// Elementwise fp32 -> bf16 hi/lo split
// ---------------------------------------------------------------------------
__global__ __launch_bounds__(256) void split_f32(
    const float4* __restrict__ src, uint2* __restrict__ dh,
    uint2* __restrict__ dl, int n4)
{
    const int i = blockIdx.x * 256 + threadIdx.x;
    if (i < n4) {
        uint32_t h[2], l[2];
        split4(src[i], h, l);
        dh[i] = make_uint2(h[0], h[1]);
        dl[i] = make_uint2(l[0], l[1]);
    }
}

// ---------------------------------------------------------------------------
// K0: per-batch context projections + gate-bias scalars
// ---------------------------------------------------------------------------
__global__ __launch_bounds__(256) void ctx_kernel(
    const float* __restrict__ ctx, const float* __restrict__ Wcq,
    const float* __restrict__ Wck, const float* __restrict__ gqc,
    const float* __restrict__ gkc)
{
    const int b = blockIdx.x;
    const int t = threadIdx.x;
    __shared__ float cs[HH];
    const float* crow = ctx + (size_t)b * HH;
    for (int i = t; i < HH; i += 256) cs[i] = crow[i];
    __syncthreads();

    for (int o = t; o < HH; o += 256) {
        const float4* wq = (const float4*)(Wcq + (size_t)o * HH);
        const float4* wk = (const float4*)(Wck + (size_t)o * HH);
        float aq = 0.f, ak = 0.f;
        #pragma unroll 4
        for (int h4 = 0; h4 < HH / 4; h4++) {
            float4 w1 = wq[h4], w2 = wk[h4];
            float e0 = cs[h4 * 4 + 0], e1 = cs[h4 * 4 + 1];
            float e2 = cs[h4 * 4 + 2], e3 = cs[h4 * 4 + 3];
            aq += w1.x * e0 + w1.y * e1 + w1.z * e2 + w1.w * e3;
            ak += w2.x * e0 + w2.y * e1 + w2.z * e2 + w2.w * e3;
        }
        g_cq[b * HH + o] = aq;
        g_ck[b * HH + o] = ak;
    }

    float pq = 0.f, pk = 0.f;
    for (int i = t; i < HH; i += 256) { pq += cs[i] * gqc[i]; pk += cs[i] * gkc[i]; }
    __shared__ float rq[8], rk[8];
    pq = warpSum(pq); pk = warpSum(pk);
    if ((t & 31) == 0) { rq[t >> 5] = pq; rk[t >> 5] = pk; }
    __syncthreads();
    if (t == 0) {
        float tq = 0.f, tk = 0.f;
        #pragma unroll
        for (int i = 0; i < 8; i++) { tq += rq[i]; tk += rk[i]; }
        g_sq[b] = tq; g_sk[b] = tk;
    }
}

// ---------------------------------------------------------------------------
// Fused gate + hat -> bf16 hi/lo
// ---------------------------------------------------------------------------
__global__ __launch_bounds__(256) void gate_hat_kernel(
    const float* __restrict__ gqh_w, const float* __restrict__ gkh_w)
{
    const int r = blockIdx.x;
    const int sel = blockIdx.y;
    const int t = threadIdx.x;
    const float* src = sel ? g_k : g_q;
    const float* gv  = sel ? gkh_w : gqh_w;
    const float* sv  = sel ? g_sk : g_sq;
    const int b = r >> 11;
    const float* cp  = (sel ? g_ck : g_cq) + b * HH;
    __nv_bfloat16* dsth = sel ? g_kh : g_qh;
    __nv_bfloat16* dstl = sel ? g_kl : g_ql;

    const float4* rowp = (const float4*)(src + (size_t)r * HH);
    float4 v = rowp[t];
    float4 gw = ((const float4*)gv)[t];
    float p = v.x * gw.x + v.y * gw.y + v.z * gw.z + v.w * gw.w;
    p = warpSum(p);
    __shared__ float red[8];
    __shared__ float gsh;
    if ((t & 31) == 0) red[t >> 5] = p;
    __syncthreads();
    if (t == 0) {
        float tot = 0.f;
        #pragma unroll
        for (int i = 0; i < 8; i++) tot += red[i];
        gsh = 1.f / (1.f + expf(-(tot + sv[b])));
    }
    __syncthreads();
    const float g = gsh;
    float4 c = ((const float4*)cp)[t];
    v.x += g * (c.x - v.x); v.y += g * (c.y - v.y);
    v.z += g * (c.z - v.z); v.w += g * (c.w - v.w);

    uint32_t h[2], l[2];
    split4(v, h, l);
    *(uint2*)(dsth + (size_t)r * HH + 4 * t) = make_uint2(h[0], h[1]);
    *(uint2*)(dstl + (size_t)r * HH + 4 * t) = make_uint2(l[0], l[1]);
}

// ---------------------------------------------------------------------------
// V transpose per batch into bf16 hi/lo
// ---------------------------------------------------------------------------
__global__ __launch_bounds__(256) void transpose_v()
{
    __shared__ float tile[32][33];
    const int z = blockIdx.z;
    const int s0 = blockIdx.x * 32, h0 = blockIdx.y * 32;
    const float* src = g_v + (size_t)z * SS * HH;
    __nv_bfloat16* dh = g_vth + (size_t)z * HH * SS;
    __nv_bfloat16* dl = g_vtl + (size_t)z * HH * SS;
    const int tx = threadIdx.x, ty = threadIdx.y;
    #pragma unroll
    for (int i = ty; i < 32; i += 8)
        tile[i][tx] = src[(size_t)(s0 + i) * HH + h0 + tx];
    __syncthreads();
    #pragma unroll
    for (int i = ty; i < 32; i += 8) {
        const float v = tile[tx][i];
        const __nv_bfloat16 hb = __float2bfloat16_rn(v);
        dh[(size_t)(h0 + i) * SS + s0 + tx] = hb;
        dl[(size_t)(h0 + i) * SS + s0 + tx] = __float2bfloat16_rn(v - __bfloat162float(hb));
    }
}

// ---------------------------------------------------------------------------
// Softmax over each scores row -> probs bf16 hi/lo. One block per row.
// ---------------------------------------------------------------------------
__global__ __launch_bounds__(256) void softmax_rows(const float* __restrict__ scores)
{
    const int row = blockIdx.x;
    const int t = threadIdx.x;
    const float4* src = (const float4*)(scores + (size_t)row * SS);
    __nv_bfloat16* dh = g_ph + (size_t)row * SS;
    __nv_bfloat16* dl = g_pl + (size_t)row * SS;

    float4 v0 = src[t], v1 = src[t + 256];
    float m = fmaxf(fmaxf(fmaxf(v0.x, v0.y), fmaxf(v0.z, v0.w)),
                    fmaxf(fmaxf(v1.x, v1.y), fmaxf(v1.z, v1.w)));
    m = warpMax(m);
    __shared__ float rm[8], rs[8];
    if ((t & 31) == 0) rm[t >> 5] = m;
    __syncthreads();
    float mm = rm[0];
    #pragma unroll
    for (int i = 1; i < 8; i++) mm = fmaxf(mm, rm[i]);

    float4 e0 = {expf(v0.x - mm), expf(v0.y - mm), expf(v0.z - mm), expf(v0.w - mm)};
    float4 e1 = {expf(v1.x - mm), expf(v1.y - mm), expf(v1.z - mm), expf(v1.w - mm)};
    float s = e0.x + e0.y + e0.z + e0.w + e1.x + e1.y + e1.z + e1.w;
    s = warpSum(s);
    if ((t & 31) == 0) rs[t >> 5] = s;
    __syncthreads();
    float tot = rs[0];
    #pragma unroll
    for (int i = 1; i < 8; i++) tot += rs[i];
    const float inv = 1.f / tot;

    float4 p0 = {e0.x * inv, e0.y * inv, e0.z * inv, e0.w * inv};
    float4 p1 = {e1.x * inv, e1.y * inv, e1.z * inv, e1.w * inv};
    uint32_t h[2], l[2];
    split4(p0, h, l);
    *(uint2*)(dh + 4 * t) = make_uint2(h[0], h[1]);
    *(uint2*)(dl + 4 * t) = make_uint2(l[0], l[1]);
    split4(p1, h, l);
    *(uint2*)(dh + 1024 + 4 * t) = make_uint2(h[0], h[1]);
    *(uint2*)(dl + 1024 + 4 * t) = make_uint2(l[0], l[1]);
}

// ---------------------------------------------------------------------------
// Launch
// ---------------------------------------------------------------------------
#define GEMM_DSMEM (2 * STAGE_BYTES)   // 81920

extern "C" void kernel_launch(void* const* d_in, const int* in_sizes, int n_in,
                              void* d_out, int out_size)
{
    const float* hidden = (const float*)d_in[0];
    const float* ctx    = (const float*)d_in[1];
    const float* Wq     = (const float*)d_in[2];
    const float* bq     = (const float*)d_in[3];
    const float* Wk     = (const float*)d_in[4];
    const float* bk     = (const float*)d_in[5];
    const float* Wv     = (const float*)d_in[6];
    const float* bv     = (const float*)d_in[7];
    const float* Wcq    = (const float*)d_in[8];
    const float* Wck    = (const float*)d_in[9];
    const float* gqh_w  = (const float*)d_in[10];
    const float* gkh_w  = (const float*)d_in[11];
    const float* gqc    = (const float*)d_in[12];
    const float* gkc    = (const float*)d_in[13];

    float* out        = (float*)d_out;                 // [B,S,H]
    float* scores_out = out + (size_t)BB * SS * HH;    // [B,S,S]

    float *pq, *pk, *pv;
    __nv_bfloat16 *phh, *phl, *pwqh, *pwql, *pwkh, *pwkl, *pwvh, *pwvl;
    __nv_bfloat16 *pqh, *pql, *pkh, *pkl, *pvth, *pvtl, *pph, *ppl;
    cudaGetSymbolAddress((void**)&pq,  g_q);
    cudaGetSymbolAddress((void**)&pk,  g_k);
    cudaGetSymbolAddress((void**)&pv,  g_v);
    cudaGetSymbolAddress((void**)&phh, g_hh);
    cudaGetSymbolAddress((void**)&phl, g_hl);
    cudaGetSymbolAddress((void**)&pwqh, g_wqh);
    cudaGetSymbolAddress((void**)&pwql, g_wql);
    cudaGetSymbolAddress((void**)&pwkh, g_wkh);
    cudaGetSymbolAddress((void**)&pwkl, g_wkl);
    cudaGetSymbolAddress((void**)&pwvh, g_wvh);
    cudaGetSymbolAddress((void**)&pwvl, g_wvl);
    cudaGetSymbolAddress((void**)&pqh, g_qh);
    cudaGetSymbolAddress((void**)&pql, g_ql);
    cudaGetSymbolAddress((void**)&pkh, g_kh);
    cudaGetSymbolAddress((void**)&pkl, g_kl);
    cudaGetSymbolAddress((void**)&pvth, g_vth);
    cudaGetSymbolAddress((void**)&pvtl, g_vtl);
    cudaGetSymbolAddress((void**)&pph, g_ph);
    cudaGetSymbolAddress((void**)&ppl, g_pl);

    cudaFuncSetAttribute(gemm_pre, cudaFuncAttributeMaxDynamicSharedMemorySize, GEMM_DSMEM);

    // Context projections + scalars
    ctx_kernel<<<BB, 256>>>(ctx, Wcq, Wck, gqc, gkc);

    // Pre-split hidden and weights to bf16 hi/lo
    const int n4h = MROWS * HH / 4;                // 4,194,304
    const int n4w = HH * HH / 4;                   // 262,144
    split_f32<<<n4h / 256, 256>>>((const float4*)hidden, (uint2*)phh, (uint2*)phl, n4h);
    split_f32<<<n4w / 256, 256>>>((const float4*)Wq, (uint2*)pwqh, (uint2*)pwql, n4w);
    split_f32<<<n4w / 256, 256>>>((const float4*)Wk, (uint2*)pwkh, (uint2*)pwkl, n4w);
    split_f32<<<n4w / 256, 256>>>((const float4*)Wv, (uint2*)pwvh, (uint2*)pwvl, n4w);

    // QKV projections
    dim3 gQKV(HH / 128, MROWS / 128, 1);
    gemm_pre<<<gQKV, 256, GEMM_DSMEM>>>(phh, phl, pwqh, pwql, bq, pq, 1.f, HH, HH, 0, 0, 0);
    gemm_pre<<<gQKV, 256, GEMM_DSMEM>>>(phh, phl, pwkh, pwkl, bk, pk, 1.f, HH, HH, 0, 0, 0);
    gemm_pre<<<gQKV, 256, GEMM_DSMEM>>>(phh, phl, pwvh, pwvl, bv, pv, 1.f, HH, HH, 0, 0, 0);

    // Gate + hat -> bf16 hi/lo
    gate_hat_kernel<<<dim3(MROWS, 2), 256>>>(gqh_w, gkh_w);

    // V transpose -> bf16 hi/lo
    transpose_v<<<dim3(SS / 32, HH / 32, BB), dim3(32, 8)>>>();

    // scores = qhat @ khat^T * 1/32 per batch
    gemm_pre<<<dim3(SS / 128, SS / 128, BB), 256, GEMM_DSMEM>>>(
        pqh, pql, pkh, pkl, nullptr, scores_out, 0.03125f, SS, HH,
        (long long)SS * HH, (long long)SS * HH, (long long)SS * SS);

    // softmax -> probs bf16 hi/lo
    softmax_rows<<<BB * SS, 256>>>(scores_out);

    // out = probs @ V per batch
    gemm_pre<<<dim3(HH / 128, SS / 128, BB), 256, GEMM_DSMEM>>>(
        pph, ppl, pvth, pvtl, nullptr, out, 1.f, HH, SS,
        (long long)SS * SS, (long long)HH * SS, (long long)SS * HH);
}